// round 9
// baseline (speedup 1.0000x reference)
#include <cuda_runtime.h>
#include <cuda_fp16.h>
#include <cstdint>

// ---------------------------------------------------------------------------
// CMA block: pool2x2 -> QKV 1x1 conv -> softmax attention (N=4096, d=64) ->
// O 1x1 conv + BN (folded, at low res) -> bilinear 2x -> lrelu -> +rgb
// Attention: fp8 e4m3 mma.sync m16n8k32 (halves tensor instruction count vs
// f16; legacy pipe on B300 is per-instruction bound at rt~15/SMSP).
// Softmax numerator uses (p-1) quantization + exact colsum(V) for precision.
// Round-8 fix: P-tile row stride 72 -> 80 bytes (ldmatrix needs 16B-aligned
// row addresses); g_SV explicitly aligned for float2 loads.
// ---------------------------------------------------------------------------

#define BB 8
#define NTOK 4096
#define DD 64
#define QSCALE 0.18033688011112042f   // (1/8) * log2(e)

// scratch (device globals: no allocation allowed)
__device__ __align__(16) unsigned char g_Q[BB * NTOK * DD];  // e4m3 [b][n][c]
__device__ __align__(16) unsigned char g_K[BB * NTOK * DD];  // e4m3 [b][n][c]
__device__ __align__(16) unsigned char g_V[BB * DD * NTOK];  // e4m3 [b][c][n]
__device__ __align__(16) float g_SV[BB * DD];                // colsum of quantized V
__device__ __align__(16) float g_Z[BB * NTOK * DD];          // attn out [b][n][c]
__device__ __align__(16) float g_Y[BB * DD * NTOK];          // o-proj   [b][c][n]

// ---- conversion helpers ----------------------------------------------------
__device__ __forceinline__ unsigned short pack_e4m3(float lo, float hi) {
    unsigned short r;
    asm("cvt.rn.satfinite.e4m3x2.f32 %0, %1, %2;" : "=h"(r) : "f"(hi), "f"(lo));
    return r;
}
__device__ __forceinline__ unsigned short h2_to_e4m3(__half2 h) {
    unsigned short r;
    asm("cvt.rn.satfinite.e4m3x2.f16x2 %0, %1;" : "=h"(r) : "r"(*(unsigned*)&h));
    return r;
}
__device__ __forceinline__ __half2 e4m3_to_h2(unsigned short q) {
    unsigned r;
    asm("cvt.rn.f16x2.e4m3x2 %0, %1;" : "=r"(r) : "h"(q));
    return *(__half2*)&r;
}
__device__ __forceinline__ __half2 cvt_h2(float lo, float hi) {
    unsigned r;
    asm("cvt.rn.f16x2.f32 %0, %1, %2;" : "=r"(r) : "f"(hi), "f"(lo));
    return *(__half2*)&r;
}
__device__ __forceinline__ __half2 hex2_h2(__half2 x) {
    unsigned r;
    asm("ex2.approx.f16x2 %0, %1;" : "=r"(r) : "r"(*(unsigned*)&x));
    return *(__half2*)&r;
}
// fp8 MMA: D(f32 x4) += A(e4m3 m16k32) * B(e4m3 k32n8)
__device__ __forceinline__ void mma_fp8(float (&d)[4], const unsigned (&a)[4],
                                        unsigned b0, unsigned b1) {
    asm volatile(
        "mma.sync.aligned.m16n8k32.row.col.f32.e4m3.e4m3.f32 "
        "{%0,%1,%2,%3}, {%4,%5,%6,%7}, {%8,%9}, {%0,%1,%2,%3};\n"
        : "+f"(d[0]), "+f"(d[1]), "+f"(d[2]), "+f"(d[3])
        : "r"(a[0]), "r"(a[1]), "r"(a[2]), "r"(a[3]), "r"(b0), "r"(b1));
}
__device__ __forceinline__ void ldsm4(unsigned& r0, unsigned& r1, unsigned& r2,
                                      unsigned& r3, uint32_t addr) {
    asm volatile("ldmatrix.sync.aligned.m8n8.x4.shared.b16 {%0,%1,%2,%3}, [%4];"
                 : "=r"(r0), "=r"(r1), "=r"(r2), "=r"(r3) : "r"(addr));
}
__device__ __forceinline__ void cp16(uint32_t s, const void* g) {
    asm volatile("cp.async.cg.shared.global [%0], [%1], 16;" :: "r"(s), "l"(g));
}
__device__ __forceinline__ void sts16(uint32_t addr, unsigned short v) {
    asm volatile("st.shared.u16 [%0], %1;" :: "r"(addr), "h"(v));
}
__device__ __forceinline__ uint32_t smem_u32(const void* p) {
    uint32_t a;
    asm("{ .reg .u64 t; cvta.to.shared.u64 t, %1; cvt.u32.u64 %0, t; }" : "=r"(a) : "l"(p));
    return a;
}

// ---------------------------------------------------------------------------
// Stage 0: zero the V colsum accumulator.
// ---------------------------------------------------------------------------
__global__ void sv_init_kernel() { g_SV[threadIdx.x] = 0.f; }

// ---------------------------------------------------------------------------
// Stage 1: pool 2x2 + QKV projection. grid (64 ds-rows, B, 2 modes).
// mode 0: Q from rgb; mode 1: K then V from freq (freq read once).
// Outputs are e4m3. V pass also accumulates exact colsum of quantized V.
// ---------------------------------------------------------------------------
__device__ __forceinline__ void proj_compute(
    const float (*xs)[64], const float (*Ws)[65], const float* bias,
    int tid, float (&acc)[4][8]) {
    int og = tid >> 3, tg = tid & 7;
    int o0 = og * 4;
    #pragma unroll
    for (int oi = 0; oi < 4; oi++) {
        float bv = bias[o0 + oi];
        #pragma unroll
        for (int ti = 0; ti < 8; ti++) acc[oi][ti] = bv;
    }
    for (int c = 0; c < 64; c++) {
        float wv[4], xv[8];
        #pragma unroll
        for (int oi = 0; oi < 4; oi++) wv[oi] = Ws[c][o0 + oi];
        #pragma unroll
        for (int ti = 0; ti < 8; ti++) xv[ti] = xs[c][ti * 8 + tg];
        #pragma unroll
        for (int oi = 0; oi < 4; oi++)
            #pragma unroll
            for (int ti = 0; ti < 8; ti++) acc[oi][ti] += wv[oi] * xv[ti];
    }
}

__global__ __launch_bounds__(128) void qkv_kernel(
    const float* __restrict__ rgb, const float* __restrict__ freq,
    const float* __restrict__ w_q, const float* __restrict__ b_q,
    const float* __restrict__ w_k, const float* __restrict__ b_k,
    const float* __restrict__ w_v, const float* __restrict__ b_v) {
    int y = blockIdx.x, b = blockIdx.y, mode = blockIdx.z;
    __shared__ float xs[64][64];   // pooled input [c][t]
    __shared__ float Ws[64][65];   // weights transposed [c][o]; reused as V staging
    int tid = threadIdx.x;
    int tg = tid & 7, o0 = (tid >> 3) * 4;

    const float* src = (mode == 0) ? rgb : freq;
    const float* base = src + (((size_t)b * 64) * 128 + 2 * y) * 128;
    for (int idx = tid; idx < 4096; idx += 128) {
        int c = idx >> 6, t = idx & 63;
        const float* p = base + (size_t)c * 128 * 128 + 2 * t;
        float2 a0 = *(const float2*)p;
        float2 a1 = *(const float2*)(p + 128);
        xs[c][t] = 0.25f * (a0.x + a0.y + a1.x + a1.y);
    }
    const float* w0 = (mode == 0) ? w_q : w_k;
    for (int idx = tid; idx < 4096; idx += 128) {
        int o = idx >> 6, c = idx & 63;
        Ws[c][o] = w0[idx];
    }
    __syncthreads();

    float acc[4][8];
    proj_compute(xs, Ws, (mode == 0) ? b_q : b_k, tid, acc);

    if (mode == 0) {   // Q: [b][n][c] e4m3, pre-scaled by QSCALE
        #pragma unroll
        for (int ti = 0; ti < 8; ti++) {
            int t = ti * 8 + tg;
            size_t rowoff = ((size_t)b * NTOK + y * 64 + t) * 64 + o0;
            unsigned short a = pack_e4m3(acc[0][ti] * QSCALE, acc[1][ti] * QSCALE);
            unsigned short bq = pack_e4m3(acc[2][ti] * QSCALE, acc[3][ti] * QSCALE);
            *(unsigned*)&g_Q[rowoff] = (unsigned)a | ((unsigned)bq << 16);
        }
        return;
    }
    // K: [b][n][c] e4m3
    #pragma unroll
    for (int ti = 0; ti < 8; ti++) {
        int t = ti * 8 + tg;
        size_t rowoff = ((size_t)b * NTOK + y * 64 + t) * 64 + o0;
        unsigned short a = pack_e4m3(acc[0][ti], acc[1][ti]);
        unsigned short bq = pack_e4m3(acc[2][ti], acc[3][ti]);
        *(unsigned*)&g_K[rowoff] = (unsigned)a | ((unsigned)bq << 16);
    }
    __syncthreads();   // all Ws reads done before reload
    for (int idx = tid; idx < 4096; idx += 128) {
        int o = idx >> 6, c = idx & 63;
        Ws[c][o] = w_v[idx];
    }
    __syncthreads();
    proj_compute(xs, Ws, b_v, tid, acc);
    // stage V (f32) into Ws [chan][tok] for coalesced quantize+store
    __syncthreads();
    #pragma unroll
    for (int oi = 0; oi < 4; oi++)
        #pragma unroll
        for (int ti = 0; ti < 8; ti++)
            Ws[o0 + oi][ti * 8 + tg] = acc[oi][ti];
    __syncthreads();
    {
        int ch = tid >> 1, half = tid & 1, tb = half * 32;
        unsigned words[8];
        float sum = 0.f;
        #pragma unroll
        for (int m = 0; m < 8; m++) {
            unsigned short lo2 = pack_e4m3(Ws[ch][tb + 4 * m], Ws[ch][tb + 4 * m + 1]);
            unsigned short hi2 = pack_e4m3(Ws[ch][tb + 4 * m + 2], Ws[ch][tb + 4 * m + 3]);
            words[m] = (unsigned)lo2 | ((unsigned)hi2 << 16);
            float2 f0 = __half22float2(e4m3_to_h2(lo2));
            float2 f1 = __half22float2(e4m3_to_h2(hi2));
            sum += (f0.x + f0.y) + (f1.x + f1.y);
        }
        unsigned char* gv = g_V + ((size_t)b * 64 + ch) * NTOK + y * 64 + tb;
        *(uint4*)gv = make_uint4(words[0], words[1], words[2], words[3]);
        *(uint4*)(gv + 16) = make_uint4(words[4], words[5], words[6], words[7]);
        float partner = __shfl_xor_sync(0xffffffffu, sum, 1);
        if (half == 0) atomicAdd(&g_SV[b * 64 + ch], sum + partner);
    }
}

// ---------------------------------------------------------------------------
// Stage 2: fused attention, fp8 mma.sync m16n8k32.
// BM=128 queries/CTA, BN=64 keys/iter, 8 warps, 2 CTA/SM.
// p' = exp2(q'.k) - 1 quantized to e4m3; z = (P'V + colsumV) / sum(p).
// SMEM: 2 stages x {K 64x80B, V 64x80B} + per-warp P tiles (16x80B).
// ---------------------------------------------------------------------------
__global__ __launch_bounds__(256, 2) void attn_kernel() {
    __shared__ __align__(16) unsigned char SM[2 * 10240 + 8 * 1280];
    int b = blockIdx.y;
    int qbase = blockIdx.x * 128;
    int tid = threadIdx.x, lane = tid & 31, warp = tid >> 5;
    int grp = lane >> 2, tig = lane & 3;

    const unsigned char* Kp = g_K + (size_t)b * NTOK * 64;
    const unsigned char* Vp = g_V + (size_t)b * 64 * NTOK;

    // Q A-fragments (e4m3, two k32 chunks) loaded directly from gmem once
    unsigned qa[2][4];
    {
        const unsigned char* Qp =
            g_Q + ((size_t)b * NTOK + qbase + warp * 16 + grp) * 64;
        #pragma unroll
        for (int c = 0; c < 2; c++) {
            qa[c][0] = *(const unsigned*)(Qp + c * 32 + 4 * tig);
            qa[c][1] = *(const unsigned*)(Qp + 8 * 64 + c * 32 + 4 * tig);
            qa[c][2] = *(const unsigned*)(Qp + c * 32 + 16 + 4 * tig);
            qa[c][3] = *(const unsigned*)(Qp + 8 * 64 + c * 32 + 16 + 4 * tig);
        }
    }

    uint32_t sb = smem_u32(SM);
    const int STG_ = 10240;               // stage stride (K 5120 + V 5120)
    uint32_t pbase = sb + 2 * 10240 + warp * 1280;   // per-warp P tile (80B rows)
    uint32_t lmKV = (uint32_t)((lane & 7) * 80 + (lane >> 3) * 16);
    // P ldmatrix lane address (chunk 0; chunk 1 at +32)
    uint32_t lmP = pbase + (uint32_t)(((lane & 7) + ((lane >> 3) & 1) * 8) * 80 +
                                      ((lane >> 4) * 16));
    uint32_t pst_lo = pbase + (uint32_t)(grp * 80 + 2 * tig);
    uint32_t pst_hi = pst_lo + 8 * 80;

    int crow = tid >> 2, cb = (tid & 3) * 16;
    auto issue = [&](int kt, int st) {
        uint32_t kd = sb + st * STG_;
        cp16(kd + crow * 80 + cb, Kp + ((size_t)kt * 64 + crow) * 64 + cb);
        cp16(kd + 5120 + crow * 80 + cb, Vp + (size_t)crow * NTOK + kt * 64 + cb);
        asm volatile("cp.async.commit_group;" ::: "memory");
    };

    float oacc[8][4];
    #pragma unroll
    for (int dt = 0; dt < 8; dt++)
        #pragma unroll
        for (int k = 0; k < 4; k++) oacc[dt][k] = 0.f;
    float den0 = 0.f, den1 = 0.f;
    const __half2 ones = __floats2half2_rn(1.f, 1.f);
    const __half2 zero2 = __floats2half2_rn(0.f, 0.f);

    issue(0, 0);

    for (int kt = 0; kt < 64; kt++) {
        int st = kt & 1;
        asm volatile("cp.async.wait_group 0;" ::: "memory");
        __syncthreads();
        if (kt + 1 < 64) issue(kt + 1, st ^ 1);

        uint32_t Kb = sb + st * STG_ + lmKV;
        uint32_t Vb = Kb + 5120;

        // S = Q K^T, softmax numerator p' -> P smem tile (e4m3)
        __half2 dacc0 = zero2, dacc1 = zero2;
        #pragma unroll
        for (int j = 0; j < 8; j++) {
            unsigned kb[4];
            ldsm4(kb[0], kb[1], kb[2], kb[3], Kb + j * 640);
            float s[4] = {0.f, 0.f, 0.f, 0.f};
            mma_fp8(s, qa[0], kb[0], kb[1]);
            mma_fp8(s, qa[1], kb[2], kb[3]);
            __half2 plo = hex2_h2(cvt_h2(s[0], s[1]));   // row grp
            __half2 phi = hex2_h2(cvt_h2(s[2], s[3]));   // row grp+8
            dacc0 = __hadd2(dacc0, plo);
            dacc1 = __hadd2(dacc1, phi);
            sts16(pst_lo + 8 * j, h2_to_e4m3(__hsub2(plo, ones)));
            sts16(pst_hi + 8 * j, h2_to_e4m3(__hsub2(phi, ones)));
        }
        {
            float2 f0 = __half22float2(dacc0);
            float2 f1 = __half22float2(dacc1);
            den0 += f0.x + f0.y;
            den1 += f1.x + f1.y;
        }
        __syncwarp();
        // P' A-fragments via ldmatrix (warp-private tile)
        unsigned pf0[4], pf1[4];
        ldsm4(pf0[0], pf0[1], pf0[2], pf0[3], lmP);
        ldsm4(pf1[0], pf1[1], pf1[2], pf1[3], lmP + 32);
        // O += P' V
        #pragma unroll
        for (int dt = 0; dt < 8; dt++) {
            unsigned vb[4];
            ldsm4(vb[0], vb[1], vb[2], vb[3], Vb + dt * 640);
            mma_fp8(oacc[dt], pf0, vb[0], vb[1]);
            mma_fp8(oacc[dt], pf1, vb[2], vb[3]);
        }
    }

    den0 += __shfl_xor_sync(0xffffffffu, den0, 1);
    den0 += __shfl_xor_sync(0xffffffffu, den0, 2);
    den1 += __shfl_xor_sync(0xffffffffu, den1, 1);
    den1 += __shfl_xor_sync(0xffffffffu, den1, 2);
    float i0 = 1.f / den0, i1 = 1.f / den1;

    const float* svp = g_SV + b * 64;
    int r0 = qbase + warp * 16 + grp, r1 = r0 + 8;
    #pragma unroll
    for (int dt = 0; dt < 8; dt++) {
        int c = dt * 8 + tig * 2;
        float2 sv = *(const float2*)(svp + c);
        *(float2*)&g_Z[((size_t)b * NTOK + r0) * 64 + c] =
            make_float2((oacc[dt][0] + sv.x) * i0, (oacc[dt][1] + sv.y) * i0);
        *(float2*)&g_Z[((size_t)b * NTOK + r1) * 64 + c] =
            make_float2((oacc[dt][2] + sv.x) * i1, (oacc[dt][3] + sv.y) * i1);
    }
}

// ---------------------------------------------------------------------------
// Stage 3a: O-projection + folded BN at 64x64 resolution. grid (64 ds-rows, B).
// ---------------------------------------------------------------------------
__global__ __launch_bounds__(128) void convo_kernel(
    const float* __restrict__ w_o, const float* __restrict__ b_o,
    const float* __restrict__ gamma, const float* __restrict__ beta,
    const float* __restrict__ mean, const float* __restrict__ var) {
    int y = blockIdx.x, b = blockIdx.y;
    __shared__ float zs[64][65];
    __shared__ float Wsm[64][65];
    __shared__ float invs[64], bsm[64];
    int tid = threadIdx.x;

    if (tid < 64) {
        float inv = gamma[tid] * rsqrtf(var[tid] + 1e-5f);
        invs[tid] = inv;
        bsm[tid] = (b_o[tid] - mean[tid]) * inv + beta[tid];
    }
    __syncthreads();
    for (int idx = tid; idx < 4096; idx += 128) {
        int o = idx >> 6, c = idx & 63;
        Wsm[c][o] = w_o[idx] * invs[o];
    }
    for (int idx = tid; idx < 4096; idx += 128) {
        int t = idx >> 6, c = idx & 63;
        zs[t][c] = g_Z[((size_t)b * NTOK + y * 64 + t) * 64 + c];
    }
    __syncthreads();

    int og = tid >> 3, tg = tid & 7;
    int o0 = og * 4;
    float acc[4][8];
    #pragma unroll
    for (int oi = 0; oi < 4; oi++) {
        float bv = bsm[o0 + oi];
        #pragma unroll
        for (int ti = 0; ti < 8; ti++) acc[oi][ti] = bv;
    }
    for (int c = 0; c < 64; c++) {
        float wv[4], xv[8];
        #pragma unroll
        for (int oi = 0; oi < 4; oi++) wv[oi] = Wsm[c][o0 + oi];
        #pragma unroll
        for (int ti = 0; ti < 8; ti++) xv[ti] = zs[ti * 8 + tg][c];
        #pragma unroll
        for (int oi = 0; oi < 4; oi++)
            #pragma unroll
            for (int ti = 0; ti < 8; ti++) acc[oi][ti] += wv[oi] * xv[ti];
    }
    #pragma unroll
    for (int oi = 0; oi < 4; oi++)
        #pragma unroll
        for (int ti = 0; ti < 8; ti++)
            g_Y[((size_t)b * 64 + o0 + oi) * NTOK + y * 64 + ti * 8 + tg] = acc[oi][ti];
}

// ---------------------------------------------------------------------------
// Stage 3b: bilinear 2x (align_corners=False) + LeakyReLU + residual.
// ---------------------------------------------------------------------------
__global__ __launch_bounds__(256) void final_kernel(
    const float* __restrict__ rgb, float* __restrict__ out) {
    int c = blockIdx.x, b = blockIdx.y;
    __shared__ float Ys[64][65];
    int tid = threadIdx.x;

    const float* Yb = g_Y + ((size_t)b * 64 + c) * NTOK;
    for (int i = tid; i < 4096; i += 256) Ys[i >> 6][i & 63] = Yb[i];
    __syncthreads();

    const float* Rb = rgb + ((size_t)b * 64 + c) * 16384;
    float* Ob = out + ((size_t)b * 64 + c) * 16384;

    #pragma unroll 4
    for (int rep = 0; rep < 16; rep++) {
        int cell = tid + rep * 256;
        int h = cell >> 6, w = cell & 63;
        int hm = max(h - 1, 0), hp = min(h + 1, 63);
        int wm = max(w - 1, 0), wp = min(w + 1, 63);
        float a0 = Ys[hm][wm], a1 = Ys[hm][w], a2 = Ys[hm][wp];
        float b0 = Ys[h][wm],  b1 = Ys[h][w],  b2 = Ys[h][wp];
        float c0 = Ys[hp][wm], c1 = Ys[hp][w], c2 = Ys[hp][wp];
        float u0 = 0.25f * a0 + 0.75f * b0;
        float u1 = 0.25f * a1 + 0.75f * b1;
        float u2 = 0.25f * a2 + 0.75f * b2;
        float d0 = 0.75f * b0 + 0.25f * c0;
        float d1 = 0.75f * b1 + 0.25f * c1;
        float d2 = 0.75f * b2 + 0.25f * c2;
        float o00 = 0.25f * u0 + 0.75f * u1, o01 = 0.75f * u1 + 0.25f * u2;
        float o10 = 0.25f * d0 + 0.75f * d1, o11 = 0.75f * d1 + 0.25f * d2;
        o00 = (o00 >= 0.f) ? o00 : 0.2f * o00;
        o01 = (o01 >= 0.f) ? o01 : 0.2f * o01;
        o10 = (o10 >= 0.f) ? o10 : 0.2f * o10;
        o11 = (o11 >= 0.f) ? o11 : 0.2f * o11;
        float2 r0 = *(const float2*)(Rb + (2 * h) * 128 + 2 * w);
        float2 r1 = *(const float2*)(Rb + (2 * h + 1) * 128 + 2 * w);
        *(float2*)(Ob + (2 * h) * 128 + 2 * w) = make_float2(r0.x + o00, r0.y + o01);
        *(float2*)(Ob + (2 * h + 1) * 128 + 2 * w) = make_float2(r1.x + o10, r1.y + o11);
    }
}

// ---------------------------------------------------------------------------
extern "C" void kernel_launch(void* const* d_in, const int* in_sizes, int n_in,
                              void* d_out, int out_size) {
    const float* rgb   = (const float*)d_in[0];
    const float* freq  = (const float*)d_in[1];
    const float* w_q   = (const float*)d_in[2];
    const float* b_q   = (const float*)d_in[3];
    const float* w_k   = (const float*)d_in[4];
    const float* b_k   = (const float*)d_in[5];
    const float* w_v   = (const float*)d_in[6];
    const float* b_v   = (const float*)d_in[7];
    const float* w_o   = (const float*)d_in[8];
    const float* b_o   = (const float*)d_in[9];
    const float* gamma = (const float*)d_in[10];
    const float* beta  = (const float*)d_in[11];
    const float* mean  = (const float*)d_in[12];
    const float* var   = (const float*)d_in[13];
    float* out = (float*)d_out;

    sv_init_kernel<<<1, 512>>>();
    qkv_kernel<<<dim3(64, 8, 2), 128>>>(rgb, freq, w_q, b_q, w_k, b_k, w_v, b_v);
    attn_kernel<<<dim3(32, 8), 256>>>();
    convo_kernel<<<dim3(64, 8), 128>>>(w_o, b_o, gamma, beta, mean, var);
    final_kernel<<<dim3(64, 8), 256>>>(rgb, out);
}

// round 10
// speedup vs baseline: 1.2945x; 1.2945x over previous
#include <cuda_runtime.h>
#include <cuda_fp16.h>
#include <cstdint>

// ---------------------------------------------------------------------------
// CMA block: pool2x2 -> QKV 1x1 conv -> softmax attention (N=4096, d=64) ->
// O 1x1 conv + BN (FUSED into attention epilogue, at low res) ->
// bilinear 2x -> lrelu -> +rgb
// Attention: legacy mma.sync f16 accumulators (tensor-pipe bound ~15cyc/HMMA;
// fp8 regressed: smem round-trip for P dominated). Conv fused at ~zero cost:
// y[r] = (O[r] @ W2^T) / den_r + bias  (division commutes with the conv).
// ---------------------------------------------------------------------------

#define BB 8
#define NTOK 4096   // 64*64 tokens per batch
#define DD 64
// scale * log2(e) folded into Q so softmax numerator = exp2(q'.k)
#define QSCALE 0.18033688011112042f

// scratch (device globals: no allocation allowed)
__device__ __align__(16) __half g_Q[BB * NTOK * DD];   // [b][n][c]
__device__ __align__(16) __half g_K[BB * NTOK * DD];   // [b][n][c]
__device__ __align__(16) __half g_V[BB * DD * NTOK];   // [b][c][n]
__device__ __align__(16) float g_Y[BB * DD * NTOK];    // conv out [b][c][n]

__device__ __forceinline__ unsigned packh(float lo, float hi) {
    __half2 h = __floats2half2_rn(lo, hi);
    return *(unsigned*)&h;
}
__device__ __forceinline__ unsigned hex2(unsigned x) {
    unsigned r; asm("ex2.approx.f16x2 %0, %1;" : "=r"(r) : "r"(x)); return r;
}
__device__ __forceinline__ __half2 uh2(unsigned x) { return *(__half2*)&x; }

// f16-accumulator MMA: D(f16x2 x2) = A(f16 m16k16) * B(f16 k16n8) + D
__device__ __forceinline__ void mma_h(unsigned (&d)[2], const unsigned (&a)[4],
                                      unsigned b0, unsigned b1) {
    asm volatile(
        "mma.sync.aligned.m16n8k16.row.col.f16.f16.f16.f16 "
        "{%0,%1}, {%2,%3,%4,%5}, {%6,%7}, {%0,%1};\n"
        : "+r"(d[0]), "+r"(d[1])
        : "r"(a[0]), "r"(a[1]), "r"(a[2]), "r"(a[3]), "r"(b0), "r"(b1));
}
// f32-accumulator MMA (epilogue conv): D(f32 x4) = A(f16) * B(f16) + D
__device__ __forceinline__ void mma_hf32(float (&d)[4], const unsigned (&a)[4],
                                         unsigned b0, unsigned b1) {
    asm volatile(
        "mma.sync.aligned.m16n8k16.row.col.f32.f16.f16.f32 "
        "{%0,%1,%2,%3}, {%4,%5,%6,%7}, {%8,%9}, {%0,%1,%2,%3};\n"
        : "+f"(d[0]), "+f"(d[1]), "+f"(d[2]), "+f"(d[3])
        : "r"(a[0]), "r"(a[1]), "r"(a[2]), "r"(a[3]), "r"(b0), "r"(b1));
}
__device__ __forceinline__ void ldsm4(unsigned& r0, unsigned& r1, unsigned& r2,
                                      unsigned& r3, uint32_t addr) {
    asm volatile("ldmatrix.sync.aligned.m8n8.x4.shared.b16 {%0,%1,%2,%3}, [%4];"
                 : "=r"(r0), "=r"(r1), "=r"(r2), "=r"(r3) : "r"(addr));
}
__device__ __forceinline__ void cp16(uint32_t s, const void* g) {
    asm volatile("cp.async.cg.shared.global [%0], [%1], 16;" :: "r"(s), "l"(g));
}
__device__ __forceinline__ uint32_t smem_u32(const void* p) {
    uint32_t a;
    asm("{ .reg .u64 t; cvta.to.shared.u64 t, %1; cvt.u32.u64 %0, t; }" : "=r"(a) : "l"(p));
    return a;
}

// ---------------------------------------------------------------------------
// Stage 1: pool 2x2 + QKV projection. grid (64 ds-rows, B, 2 modes).
// mode 0: Q from rgb; mode 1: K then V from freq (freq read ONCE).
// ---------------------------------------------------------------------------
__device__ __forceinline__ void proj_compute(
    const float (*xs)[64], const float (*Ws)[65], const float* bias,
    int tid, float (&acc)[4][8]) {
    int og = tid >> 3, tg = tid & 7;
    int o0 = og * 4;
    #pragma unroll
    for (int oi = 0; oi < 4; oi++) {
        float bv = bias[o0 + oi];
        #pragma unroll
        for (int ti = 0; ti < 8; ti++) acc[oi][ti] = bv;
    }
    for (int c = 0; c < 64; c++) {
        float wv[4], xv[8];
        #pragma unroll
        for (int oi = 0; oi < 4; oi++) wv[oi] = Ws[c][o0 + oi];
        #pragma unroll
        for (int ti = 0; ti < 8; ti++) xv[ti] = xs[c][ti * 8 + tg];
        #pragma unroll
        for (int oi = 0; oi < 4; oi++)
            #pragma unroll
            for (int ti = 0; ti < 8; ti++) acc[oi][ti] += wv[oi] * xv[ti];
    }
}

__global__ __launch_bounds__(128) void qkv_kernel(
    const float* __restrict__ rgb, const float* __restrict__ freq,
    const float* __restrict__ w_q, const float* __restrict__ b_q,
    const float* __restrict__ w_k, const float* __restrict__ b_k,
    const float* __restrict__ w_v, const float* __restrict__ b_v) {
    int y = blockIdx.x, b = blockIdx.y, mode = blockIdx.z;
    __shared__ float xs[64][64];   // pooled input [c][t]
    __shared__ float Ws[64][65];   // weights transposed [c][o]
    int tid = threadIdx.x;
    int tg = tid & 7, o0 = (tid >> 3) * 4;

    const float* src = (mode == 0) ? rgb : freq;
    const float* base = src + (((size_t)b * 64) * 128 + 2 * y) * 128;
    for (int idx = tid; idx < 4096; idx += 128) {
        int c = idx >> 6, t = idx & 63;
        const float* p = base + (size_t)c * 128 * 128 + 2 * t;
        float2 a0 = *(const float2*)p;
        float2 a1 = *(const float2*)(p + 128);
        xs[c][t] = 0.25f * (a0.x + a0.y + a1.x + a1.y);
    }
    const float* w0 = (mode == 0) ? w_q : w_k;
    for (int idx = tid; idx < 4096; idx += 128) {
        int o = idx >> 6, c = idx & 63;
        Ws[c][o] = w0[idx];
    }
    __syncthreads();

    float acc[4][8];
    proj_compute(xs, Ws, (mode == 0) ? b_q : b_k, tid, acc);

    if (mode == 0) {   // Q: [b][n][c], pre-scaled by QSCALE
        #pragma unroll
        for (int ti = 0; ti < 8; ti++) {
            int t = ti * 8 + tg;
            size_t rowoff = ((size_t)b * NTOK + y * 64 + t) * 64 + o0;
            #pragma unroll
            for (int oi = 0; oi < 4; oi += 2)
                *(unsigned*)&g_Q[rowoff + oi] =
                    packh(acc[oi][ti] * QSCALE, acc[oi + 1][ti] * QSCALE);
        }
        return;
    }
    // K: [b][n][c]
    #pragma unroll
    for (int ti = 0; ti < 8; ti++) {
        int t = ti * 8 + tg;
        size_t rowoff = ((size_t)b * NTOK + y * 64 + t) * 64 + o0;
        #pragma unroll
        for (int oi = 0; oi < 4; oi += 2)
            *(unsigned*)&g_K[rowoff + oi] = packh(acc[oi][ti], acc[oi + 1][ti]);
    }
    __syncthreads();   // all Ws reads done before reload
    for (int idx = tid; idx < 4096; idx += 128) {
        int o = idx >> 6, c = idx & 63;
        Ws[c][o] = w_v[idx];
    }
    __syncthreads();
    proj_compute(xs, Ws, b_v, tid, acc);
    // V: [b][c][n]
    #pragma unroll
    for (int oi = 0; oi < 4; oi++)
        #pragma unroll
        for (int ti = 0; ti < 8; ti++) {
            int t = ti * 8 + tg;
            g_V[((size_t)b * 64 + o0 + oi) * NTOK + y * 64 + t] =
                __float2half_rn(acc[oi][ti]);
        }
}

// ---------------------------------------------------------------------------
// Stage 2: fused attention + O-projection + BN.
// BM=128 queries per CTA, BN=64 keys/iter, 8 warps, 2 CTA/SM.
// No max-subtraction (logits tiny): p = exp2(q'.k).
// Epilogue: y[r][o] = (O[r] @ W2[o]) / den_r + bias[o]  (conv before divide),
// where W2 = w_o * bn_scale (f16), bias = BN-folded. O f16 fragments reused
// directly as conv A-fragments. Writes g_Y [b][o][tok].
// ---------------------------------------------------------------------------
__global__ __launch_bounds__(256, 2) void attn_kernel(
    const float* __restrict__ w_o, const float* __restrict__ b_o,
    const float* __restrict__ gamma, const float* __restrict__ beta,
    const float* __restrict__ mean, const float* __restrict__ var) {
    int b = blockIdx.y;
    int qbase = blockIdx.x * 128;
    // [stage][K/V][row][72]: row stride 144B (conflict-free for ldmatrix)
    __shared__ __align__(16) __half KVs[2][2][64][72];
    __shared__ __align__(16) __half Wt[64][72];   // W2 [o][c], BN-folded
    __shared__ float invs[64], bsm[64];

    int tid = threadIdx.x, lane = tid & 31, warp = tid >> 5;
    int grp = lane >> 2, tig = lane & 3;

    const __half* Kp = g_K + (size_t)b * NTOK * 64;
    const __half* Vp = g_V + (size_t)b * 64 * NTOK;

    uint32_t sb = (uint32_t)__cvta_generic_to_shared(&KVs[0][0][0][0]);
    const int STG = 2 * 64 * 144;   // stage stride bytes
    const int KVD = 64 * 144;       // K->V stride bytes
    uint32_t lmoff = (uint32_t)((lane & 7) * 144 + (lane >> 3) * 16);

    int r0i = tid, r1i = tid + 256;
    int row0 = r0i >> 3, ch0 = r0i & 7, row1 = r1i >> 3, ch1 = r1i & 7;

    auto issue = [&](int kt, int st) {
        uint32_t kd = sb + st * STG;
        uint32_t vd = kd + KVD;
        cp16(kd + row0 * 144 + ch0 * 16, Kp + (kt * 64 + row0) * 64 + ch0 * 8);
        cp16(kd + row1 * 144 + ch1 * 16, Kp + (kt * 64 + row1) * 64 + ch1 * 8);
        cp16(vd + row0 * 144 + ch0 * 16, Vp + (size_t)row0 * NTOK + kt * 64 + ch0 * 8);
        cp16(vd + row1 * 144 + ch1 * 16, Vp + (size_t)row1 * NTOK + kt * 64 + ch1 * 8);
        asm volatile("cp.async.commit_group;" ::: "memory");
    };

    issue(0, 0);   // start DRAM fetch ASAP

    // BN fold + weight load (visible after first in-loop __syncthreads)
    if (tid < 64) {
        float inv = gamma[tid] * rsqrtf(var[tid] + 1e-5f);
        invs[tid] = inv;
        bsm[tid] = (b_o[tid] - mean[tid]) * inv + beta[tid];
    }
    __syncthreads();
    for (int idx = tid; idx < 4096; idx += 256) {
        int o = idx >> 6, c = idx & 63;
        Wt[o][c] = __float2half_rn(w_o[idx] * invs[o]);
    }

    // A-fragments for Q loaded directly from gmem (once)
    unsigned qa[4][4];
    {
        const __half* Qp = g_Q + ((size_t)b * NTOK + qbase + warp * 16 + grp) * 64;
        #pragma unroll
        for (int ks = 0; ks < 4; ks++) {
            qa[ks][0] = *(const unsigned*)(Qp + ks * 16 + tig * 2);
            qa[ks][1] = *(const unsigned*)(Qp + 8 * 64 + ks * 16 + tig * 2);
            qa[ks][2] = *(const unsigned*)(Qp + ks * 16 + 8 + tig * 2);
            qa[ks][3] = *(const unsigned*)(Qp + 8 * 64 + ks * 16 + 8 + tig * 2);
        }
    }

    unsigned oacc[8][2];
    #pragma unroll
    for (int dt = 0; dt < 8; dt++) { oacc[dt][0] = 0u; oacc[dt][1] = 0u; }
    float den0 = 0.f, den1 = 0.f;

    for (int kt = 0; kt < 64; kt++) {
        int st = kt & 1;
        asm volatile("cp.async.wait_group 0;" ::: "memory");
        __syncthreads();
        if (kt + 1 < 64) issue(kt + 1, st ^ 1);

        uint32_t Kb = sb + st * STG + lmoff;
        uint32_t Vb = Kb + KVD;

        unsigned pa[4][4];
        #pragma unroll
        for (int j = 0; j < 4; j++) {
            unsigned s0[2] = {0u, 0u}, s1[2] = {0u, 0u};
            unsigned kb0[8], kb1[8];
            ldsm4(kb0[0], kb0[1], kb0[2], kb0[3], Kb + (2 * j) * 1152);
            ldsm4(kb0[4], kb0[5], kb0[6], kb0[7], Kb + (2 * j) * 1152 + 64);
            ldsm4(kb1[0], kb1[1], kb1[2], kb1[3], Kb + (2 * j + 1) * 1152);
            ldsm4(kb1[4], kb1[5], kb1[6], kb1[7], Kb + (2 * j + 1) * 1152 + 64);
            #pragma unroll
            for (int ks = 0; ks < 4; ks++) {
                mma_h(s0, qa[ks], kb0[2 * ks], kb0[2 * ks + 1]);
                mma_h(s1, qa[ks], kb1[2 * ks], kb1[2 * ks + 1]);
            }
            pa[j][0] = hex2(s0[0]);   // rows grp,   tile 2j
            pa[j][1] = hex2(s0[1]);   // rows grp+8
            pa[j][2] = hex2(s1[0]);   // tile 2j+1
            pa[j][3] = hex2(s1[1]);
        }
        // denominator: within-iter f16 trees, cross-iter f32
        {
            __half2 a0 = __hadd2(__hadd2(uh2(pa[0][0]), uh2(pa[0][2])),
                                 __hadd2(uh2(pa[1][0]), uh2(pa[1][2])));
            __half2 a1 = __hadd2(__hadd2(uh2(pa[2][0]), uh2(pa[2][2])),
                                 __hadd2(uh2(pa[3][0]), uh2(pa[3][2])));
            float2 f0 = __half22float2(__hadd2(a0, a1));
            den0 += f0.x + f0.y;
            __half2 b0h = __hadd2(__hadd2(uh2(pa[0][1]), uh2(pa[0][3])),
                                  __hadd2(uh2(pa[1][1]), uh2(pa[1][3])));
            __half2 b1h = __hadd2(__hadd2(uh2(pa[2][1]), uh2(pa[2][3])),
                                  __hadd2(uh2(pa[3][1]), uh2(pa[3][3])));
            float2 f1 = __half22float2(__hadd2(b0h, b1h));
            den1 += f1.x + f1.y;
        }
        // O += P @ V
        #pragma unroll
        for (int dt = 0; dt < 8; dt++) {
            unsigned vb[8];
            ldsm4(vb[0], vb[1], vb[2], vb[3], Vb + dt * 1152);
            ldsm4(vb[4], vb[5], vb[6], vb[7], Vb + dt * 1152 + 64);
            #pragma unroll
            for (int j = 0; j < 4; j++)
                mma_h(oacc[dt], pa[j], vb[2 * j], vb[2 * j + 1]);
        }
    }

    den0 += __shfl_xor_sync(0xffffffffu, den0, 1);
    den0 += __shfl_xor_sync(0xffffffffu, den0, 2);
    den1 += __shfl_xor_sync(0xffffffffu, den1, 1);
    den1 += __shfl_xor_sync(0xffffffffu, den1, 2);
    float i0 = 1.f / den0, i1 = 1.f / den1;

    // ---- fused O-projection + BN epilogue ----
    // conv A-fragments = oacc f16 fragments (k = channel dim):
    // af[ks] covers k=16ks..16ks+15 from oacc tiles 2ks, 2ks+1.
    unsigned af[4][4];
    #pragma unroll
    for (int ks = 0; ks < 4; ks++) {
        af[ks][0] = oacc[2 * ks][0];
        af[ks][1] = oacc[2 * ks][1];
        af[ks][2] = oacc[2 * ks + 1][0];
        af[ks][3] = oacc[2 * ks + 1][1];
    }
    uint32_t Wb = smem_u32(&Wt[0][0]) + lmoff;
    int r0 = qbase + warp * 16 + grp, r1 = r0 + 8;
    float* Yb = g_Y + (size_t)b * 64 * NTOK;
    #pragma unroll
    for (int j = 0; j < 8; j++) {
        unsigned wb[8];
        ldsm4(wb[0], wb[1], wb[2], wb[3], Wb + j * 1152);
        ldsm4(wb[4], wb[5], wb[6], wb[7], Wb + j * 1152 + 64);
        float acc[4] = {0.f, 0.f, 0.f, 0.f};
        #pragma unroll
        for (int ks = 0; ks < 4; ks++)
            mma_hf32(acc, af[ks], wb[2 * ks], wb[2 * ks + 1]);
        int oo = 8 * j + 2 * tig;
        float bz0 = bsm[oo], bz1 = bsm[oo + 1];
        Yb[(size_t)oo * NTOK + r0]       = acc[0] * i0 + bz0;
        Yb[(size_t)(oo + 1) * NTOK + r0] = acc[1] * i0 + bz1;
        Yb[(size_t)oo * NTOK + r1]       = acc[2] * i1 + bz0;
        Yb[(size_t)(oo + 1) * NTOK + r1] = acc[3] * i1 + bz1;
    }
}

// ---------------------------------------------------------------------------
// Stage 3: bilinear 2x (align_corners=False) + LeakyReLU + residual.
// One CTA per (channel, batch); Y plane staged in smem; coalesced I/O.
// 512 threads, fully unrolled reps for front-batched LDGs (MLP up).
// ---------------------------------------------------------------------------
__global__ __launch_bounds__(512) void final_kernel(
    const float* __restrict__ rgb, float* __restrict__ out) {
    int c = blockIdx.x, b = blockIdx.y;
    __shared__ float Ys[64][65];
    int tid = threadIdx.x;

    const float* Yb = g_Y + ((size_t)b * 64 + c) * NTOK;
    for (int i = tid; i < 4096; i += 512) Ys[i >> 6][i & 63] = Yb[i];
    __syncthreads();

    const float* Rb = rgb + ((size_t)b * 64 + c) * 16384;
    float* Ob = out + ((size_t)b * 64 + c) * 16384;

    #pragma unroll
    for (int rep = 0; rep < 8; rep++) {
        int cell = tid + rep * 512;
        int h = cell >> 6, w = cell & 63;
        int hm = max(h - 1, 0), hp = min(h + 1, 63);
        int wm = max(w - 1, 0), wp = min(w + 1, 63);
        float a0 = Ys[hm][wm], a1 = Ys[hm][w], a2 = Ys[hm][wp];
        float b0 = Ys[h][wm],  b1 = Ys[h][w],  b2 = Ys[h][wp];
        float c0 = Ys[hp][wm], c1 = Ys[hp][w], c2 = Ys[hp][wp];
        float u0 = 0.25f * a0 + 0.75f * b0;
        float u1 = 0.25f * a1 + 0.75f * b1;
        float u2 = 0.25f * a2 + 0.75f * b2;
        float d0 = 0.75f * b0 + 0.25f * c0;
        float d1 = 0.75f * b1 + 0.25f * c1;
        float d2 = 0.75f * b2 + 0.25f * c2;
        float o00 = 0.25f * u0 + 0.75f * u1, o01 = 0.75f * u1 + 0.25f * u2;
        float o10 = 0.25f * d0 + 0.75f * d1, o11 = 0.75f * d1 + 0.25f * d2;
        o00 = (o00 >= 0.f) ? o00 : 0.2f * o00;
        o01 = (o01 >= 0.f) ? o01 : 0.2f * o01;
        o10 = (o10 >= 0.f) ? o10 : 0.2f * o10;
        o11 = (o11 >= 0.f) ? o11 : 0.2f * o11;
        float2 r0 = *(const float2*)(Rb + (2 * h) * 128 + 2 * w);
        float2 r1 = *(const float2*)(Rb + (2 * h + 1) * 128 + 2 * w);
        *(float2*)(Ob + (2 * h) * 128 + 2 * w) = make_float2(r0.x + o00, r0.y + o01);
        *(float2*)(Ob + (2 * h + 1) * 128 + 2 * w) = make_float2(r1.x + o10, r1.y + o11);
    }
}

// ---------------------------------------------------------------------------
extern "C" void kernel_launch(void* const* d_in, const int* in_sizes, int n_in,
                              void* d_out, int out_size) {
    const float* rgb   = (const float*)d_in[0];
    const float* freq  = (const float*)d_in[1];
    const float* w_q   = (const float*)d_in[2];
    const float* b_q   = (const float*)d_in[3];
    const float* w_k   = (const float*)d_in[4];
    const float* b_k   = (const float*)d_in[5];
    const float* w_v   = (const float*)d_in[6];
    const float* b_v   = (const float*)d_in[7];
    const float* w_o   = (const float*)d_in[8];
    const float* b_o   = (const float*)d_in[9];
    const float* gamma = (const float*)d_in[10];
    const float* beta  = (const float*)d_in[11];
    const float* mean  = (const float*)d_in[12];
    const float* var   = (const float*)d_in[13];
    float* out = (float*)d_out;

    qkv_kernel<<<dim3(64, 8, 2), 128>>>(rgb, freq, w_q, b_q, w_k, b_k, w_v, b_v);
    attn_kernel<<<dim3(32, 8), 256>>>(w_o, b_o, gamma, beta, mean, var);
    final_kernel<<<dim3(64, 8), 512>>>(rgb, out);
}

// round 11
// speedup vs baseline: 1.4626x; 1.1298x over previous
#include <cuda_runtime.h>
#include <cuda_fp16.h>
#include <cstdint>

// ---------------------------------------------------------------------------
// CMA block: pool2x2 -> QKV 1x1 conv (tensor-core) -> softmax attention
// (N=4096, d=64) -> O 1x1 conv + BN (fused into attention epilogue) ->
// bilinear 2x -> lrelu -> +rgb
// Attention: legacy mma.sync f16 accumulators (tensor-pipe bound ~15cyc/HMMA).
// QKV now also on tensor cores: one CTA pools 128 tokens of rgb+freq into f16
// smem and runs 3 small GEMMs with the same ldmatrix operand patterns as attn.
// ---------------------------------------------------------------------------

#define BB 8
#define NTOK 4096   // 64*64 tokens per batch
#define DD 64
// scale * log2(e) folded into Q so softmax numerator = exp2(q'.k)
#define QSCALE 0.18033688011112042f

// scratch (device globals: no allocation allowed)
__device__ __align__(16) __half g_Q[BB * NTOK * DD];   // [b][n][c]
__device__ __align__(16) __half g_K[BB * NTOK * DD];   // [b][n][c]
__device__ __align__(16) __half g_V[BB * DD * NTOK];   // [b][c][n]
__device__ __align__(16) float g_Y[BB * DD * NTOK];    // conv out [b][c][n]

__device__ __forceinline__ unsigned packh(float lo, float hi) {
    __half2 h = __floats2half2_rn(lo, hi);
    return *(unsigned*)&h;
}
__device__ __forceinline__ unsigned hex2(unsigned x) {
    unsigned r; asm("ex2.approx.f16x2 %0, %1;" : "=r"(r) : "r"(x)); return r;
}
__device__ __forceinline__ __half2 uh2(unsigned x) { return *(__half2*)&x; }

// f16-accumulator MMA: D(f16x2 x2) = A(f16 m16k16) * B(f16 k16n8) + D
__device__ __forceinline__ void mma_h(unsigned (&d)[2], const unsigned (&a)[4],
                                      unsigned b0, unsigned b1) {
    asm volatile(
        "mma.sync.aligned.m16n8k16.row.col.f16.f16.f16.f16 "
        "{%0,%1}, {%2,%3,%4,%5}, {%6,%7}, {%0,%1};\n"
        : "+r"(d[0]), "+r"(d[1])
        : "r"(a[0]), "r"(a[1]), "r"(a[2]), "r"(a[3]), "r"(b0), "r"(b1));
}
// f32-accumulator MMA: D(f32 x4) = A(f16) * B(f16) + D
__device__ __forceinline__ void mma_hf32(float (&d)[4], const unsigned (&a)[4],
                                         unsigned b0, unsigned b1) {
    asm volatile(
        "mma.sync.aligned.m16n8k16.row.col.f32.f16.f16.f32 "
        "{%0,%1,%2,%3}, {%4,%5,%6,%7}, {%8,%9}, {%0,%1,%2,%3};\n"
        : "+f"(d[0]), "+f"(d[1]), "+f"(d[2]), "+f"(d[3])
        : "r"(a[0]), "r"(a[1]), "r"(a[2]), "r"(a[3]), "r"(b0), "r"(b1));
}
__device__ __forceinline__ void ldsm4(unsigned& r0, unsigned& r1, unsigned& r2,
                                      unsigned& r3, uint32_t addr) {
    asm volatile("ldmatrix.sync.aligned.m8n8.x4.shared.b16 {%0,%1,%2,%3}, [%4];"
                 : "=r"(r0), "=r"(r1), "=r"(r2), "=r"(r3) : "r"(addr));
}
__device__ __forceinline__ void cp16(uint32_t s, const void* g) {
    asm volatile("cp.async.cg.shared.global [%0], [%1], 16;" :: "r"(s), "l"(g));
}
__device__ __forceinline__ uint32_t smem_u32(const void* p) {
    uint32_t a;
    asm("{ .reg .u64 t; cvta.to.shared.u64 t, %1; cvt.u32.u64 %0, t; }" : "=r"(a) : "l"(p));
    return a;
}

// ---------------------------------------------------------------------------
// Stage 1: pool 2x2 + QKV projection on tensor cores.
// grid (32 token-slabs, B), 128 threads (4 warps).
// Each CTA: tokens [yp*128, yp*128+128) = 2 ds-rows.
// smem (dynamic): XR[128][72] f16 (pooled rgb, [t][c]), XF same for freq,
//                 WQ/WK/WV [64][72] f16 ([o][c]).
// GEMM Q/K: A = X (rows=t), B = W (rows=o)  -> out [t][o] = g_Q/g_K layout.
// GEMM V:   A = WV (rows=o), B = XF (rows=t) -> out [o][t] = g_V layout.
// All operands use the ldmatrix patterns proven in attn_kernel (144B rows).
// ---------------------------------------------------------------------------
#define QKV_SMEM (2 * 128 * 72 * 2 + 3 * 64 * 72 * 2)   // 64512 bytes

__device__ __forceinline__ void gemm_tok_out(
    uint32_t xb, uint32_t wb_, const float* __restrict__ bias, float scale,
    __half* __restrict__ out /* token-0 of CTA, [t][64] */, int warp, int lane) {
    int grp = lane >> 2, tig = lane & 3;
    int t0 = warp * 32;
    #pragma unroll
    for (int mt = 0; mt < 2; mt++) {
        unsigned a[4][4];
        uint32_t ab = xb + (uint32_t)((t0 + mt * 16 + (lane & 15)) * 144 +
                                      (lane >> 4) * 16);
        #pragma unroll
        for (int ks = 0; ks < 4; ks++)
            ldsm4(a[ks][0], a[ks][1], a[ks][2], a[ks][3], ab + ks * 32);
        int tr = t0 + mt * 16 + grp;
        #pragma unroll
        for (int j = 0; j < 8; j++) {
            unsigned wr[8];
            uint32_t bb = wb_ + (uint32_t)((8 * j + (lane & 7)) * 144 +
                                           (lane >> 3) * 16);
            ldsm4(wr[0], wr[1], wr[2], wr[3], bb);
            ldsm4(wr[4], wr[5], wr[6], wr[7], bb + 64);
            float acc[4] = {0.f, 0.f, 0.f, 0.f};
            #pragma unroll
            for (int ks = 0; ks < 4; ks++)
                mma_hf32(acc, a[ks], wr[2 * ks], wr[2 * ks + 1]);
            int oo = 8 * j + 2 * tig;
            float bz0 = __ldg(bias + oo), bz1 = __ldg(bias + oo + 1);
            *(unsigned*)&out[tr * 64 + oo] =
                packh((acc[0] + bz0) * scale, (acc[1] + bz1) * scale);
            *(unsigned*)&out[(tr + 8) * 64 + oo] =
                packh((acc[2] + bz0) * scale, (acc[3] + bz1) * scale);
        }
    }
}

__global__ __launch_bounds__(128) void qkv_kernel(
    const float* __restrict__ rgb, const float* __restrict__ freq,
    const float* __restrict__ w_q, const float* __restrict__ b_q,
    const float* __restrict__ w_k, const float* __restrict__ b_k,
    const float* __restrict__ w_v, const float* __restrict__ b_v) {
    extern __shared__ __half dynsm[];
    __half* XR = dynsm;                 // [128][72]
    __half* XF = XR + 128 * 72;
    __half* WQ = XF + 128 * 72;         // [64][72]
    __half* WK = WQ + 64 * 72;
    __half* WV = WK + 64 * 72;

    int yp = blockIdx.x, b = blockIdx.y;
    int tid = threadIdx.x, lane = tid & 31, warp = tid >> 5;

    // pooling: idx over (c-pair 0..31, t 0..127); coalesced gmem, u32 smem
    #pragma unroll 4
    for (int i = 0; i < 32; i++) {
        int idx = tid + i * 128;
        int cp = idx >> 7, t = idx & 127;
        int c0 = cp * 2;
        int yr = 2 * yp + (t >> 6), x = t & 63;
        size_t off = (((size_t)(b * 64 + c0) * 128) + 2 * yr) * 128 + 2 * x;
        const float* pr = rgb + off;
        const float* pf = freq + off;
        float2 r00 = *(const float2*)pr;
        float2 r01 = *(const float2*)(pr + 128);
        float2 r10 = *(const float2*)(pr + 16384);
        float2 r11 = *(const float2*)(pr + 16384 + 128);
        *(unsigned*)&XR[t * 72 + c0] =
            packh(0.25f * (r00.x + r00.y + r01.x + r01.y),
                  0.25f * (r10.x + r10.y + r11.x + r11.y));
        float2 f00 = *(const float2*)pf;
        float2 f01 = *(const float2*)(pf + 128);
        float2 f10 = *(const float2*)(pf + 16384);
        float2 f11 = *(const float2*)(pf + 16384 + 128);
        *(unsigned*)&XF[t * 72 + c0] =
            packh(0.25f * (f00.x + f00.y + f01.x + f01.y),
                  0.25f * (f10.x + f10.y + f11.x + f11.y));
    }
    // weights [o][c] f16
    for (int i = tid; i < 4096; i += 128) {
        int o = i >> 6, c = i & 63;
        WQ[o * 72 + c] = __float2half_rn(w_q[i]);
        WK[o * 72 + c] = __float2half_rn(w_k[i]);
        WV[o * 72 + c] = __float2half_rn(w_v[i]);
    }
    __syncthreads();

    uint32_t xr = smem_u32(XR), xf = smem_u32(XF);
    uint32_t wq = smem_u32(WQ), wk = smem_u32(WK), wv = smem_u32(WV);

    // Q and K: out [t][o]
    gemm_tok_out(xr, wq, b_q, QSCALE,
                 g_Q + ((size_t)b * NTOK + yp * 128) * 64, warp, lane);
    gemm_tok_out(xf, wk, b_k, 1.0f,
                 g_K + ((size_t)b * NTOK + yp * 128) * 64, warp, lane);

    // V: A = WV (rows=o), B = XF (rows=t) -> out [o][t]
    {
        int grp = lane >> 2, tig = lane & 3;
        int o0 = warp * 16;
        unsigned a[4][4];
        uint32_t ab = wv + (uint32_t)((o0 + (lane & 15)) * 144 + (lane >> 4) * 16);
        #pragma unroll
        for (int ks = 0; ks < 4; ks++)
            ldsm4(a[ks][0], a[ks][1], a[ks][2], a[ks][3], ab + ks * 32);
        float bv0 = __ldg(b_v + o0 + grp), bv1 = __ldg(b_v + o0 + grp + 8);
        __half* Vb = g_V + ((size_t)b * 64) * NTOK + yp * 128;
        #pragma unroll
        for (int j = 0; j < 16; j++) {
            unsigned wr[8];
            uint32_t bb = xf + (uint32_t)((8 * j + (lane & 7)) * 144 +
                                          (lane >> 3) * 16);
            ldsm4(wr[0], wr[1], wr[2], wr[3], bb);
            ldsm4(wr[4], wr[5], wr[6], wr[7], bb + 64);
            float acc[4] = {0.f, 0.f, 0.f, 0.f};
            #pragma unroll
            for (int ks = 0; ks < 4; ks++)
                mma_hf32(acc, a[ks], wr[2 * ks], wr[2 * ks + 1]);
            int tt = 8 * j + 2 * tig;
            *(unsigned*)&Vb[(size_t)(o0 + grp) * NTOK + tt] =
                packh(acc[0] + bv0, acc[1] + bv0);
            *(unsigned*)&Vb[(size_t)(o0 + grp + 8) * NTOK + tt] =
                packh(acc[2] + bv1, acc[3] + bv1);
        }
    }
}

// ---------------------------------------------------------------------------
// Stage 2: fused attention + O-projection + BN.
// BM=128 queries per CTA, BN=64 keys/iter, 8 warps, 2 CTA/SM.
// No max-subtraction (logits tiny): p = exp2(q'.k).
// Epilogue: y[r][o] = (O[r] @ W2[o]) / den_r + bias[o], W2 BN-folded f16.
// ---------------------------------------------------------------------------
__global__ __launch_bounds__(256, 2) void attn_kernel(
    const float* __restrict__ w_o, const float* __restrict__ b_o,
    const float* __restrict__ gamma, const float* __restrict__ beta,
    const float* __restrict__ mean, const float* __restrict__ var) {
    int b = blockIdx.y;
    int qbase = blockIdx.x * 128;
    __shared__ __align__(16) __half KVs[2][2][64][72];
    __shared__ __align__(16) __half Wt[64][72];   // W2 [o][c], BN-folded
    __shared__ float invs[64], bsm[64];

    int tid = threadIdx.x, lane = tid & 31, warp = tid >> 5;
    int grp = lane >> 2, tig = lane & 3;

    const __half* Kp = g_K + (size_t)b * NTOK * 64;
    const __half* Vp = g_V + (size_t)b * 64 * NTOK;

    uint32_t sb = (uint32_t)__cvta_generic_to_shared(&KVs[0][0][0][0]);
    const int STG = 2 * 64 * 144;
    const int KVD = 64 * 144;
    uint32_t lmoff = (uint32_t)((lane & 7) * 144 + (lane >> 3) * 16);

    int r0i = tid, r1i = tid + 256;
    int row0 = r0i >> 3, ch0 = r0i & 7, row1 = r1i >> 3, ch1 = r1i & 7;

    auto issue = [&](int kt, int st) {
        uint32_t kd = sb + st * STG;
        uint32_t vd = kd + KVD;
        cp16(kd + row0 * 144 + ch0 * 16, Kp + (kt * 64 + row0) * 64 + ch0 * 8);
        cp16(kd + row1 * 144 + ch1 * 16, Kp + (kt * 64 + row1) * 64 + ch1 * 8);
        cp16(vd + row0 * 144 + ch0 * 16, Vp + (size_t)row0 * NTOK + kt * 64 + ch0 * 8);
        cp16(vd + row1 * 144 + ch1 * 16, Vp + (size_t)row1 * NTOK + kt * 64 + ch1 * 8);
        asm volatile("cp.async.commit_group;" ::: "memory");
    };

    issue(0, 0);

    if (tid < 64) {
        float inv = gamma[tid] * rsqrtf(var[tid] + 1e-5f);
        invs[tid] = inv;
        bsm[tid] = (b_o[tid] - mean[tid]) * inv + beta[tid];
    }
    __syncthreads();
    for (int idx = tid; idx < 4096; idx += 256) {
        int o = idx >> 6, c = idx & 63;
        Wt[o][c] = __float2half_rn(w_o[idx] * invs[o]);
    }

    unsigned qa[4][4];
    {
        const __half* Qp = g_Q + ((size_t)b * NTOK + qbase + warp * 16 + grp) * 64;
        #pragma unroll
        for (int ks = 0; ks < 4; ks++) {
            qa[ks][0] = *(const unsigned*)(Qp + ks * 16 + tig * 2);
            qa[ks][1] = *(const unsigned*)(Qp + 8 * 64 + ks * 16 + tig * 2);
            qa[ks][2] = *(const unsigned*)(Qp + ks * 16 + 8 + tig * 2);
            qa[ks][3] = *(const unsigned*)(Qp + 8 * 64 + ks * 16 + 8 + tig * 2);
        }
    }

    unsigned oacc[8][2];
    #pragma unroll
    for (int dt = 0; dt < 8; dt++) { oacc[dt][0] = 0u; oacc[dt][1] = 0u; }
    float den0 = 0.f, den1 = 0.f;

    for (int kt = 0; kt < 64; kt++) {
        int st = kt & 1;
        asm volatile("cp.async.wait_group 0;" ::: "memory");
        __syncthreads();
        if (kt + 1 < 64) issue(kt + 1, st ^ 1);

        uint32_t Kb = sb + st * STG + lmoff;
        uint32_t Vb = Kb + KVD;

        unsigned pa[4][4];
        #pragma unroll
        for (int j = 0; j < 4; j++) {
            unsigned s0[2] = {0u, 0u}, s1[2] = {0u, 0u};
            unsigned kb0[8], kb1[8];
            ldsm4(kb0[0], kb0[1], kb0[2], kb0[3], Kb + (2 * j) * 1152);
            ldsm4(kb0[4], kb0[5], kb0[6], kb0[7], Kb + (2 * j) * 1152 + 64);
            ldsm4(kb1[0], kb1[1], kb1[2], kb1[3], Kb + (2 * j + 1) * 1152);
            ldsm4(kb1[4], kb1[5], kb1[6], kb1[7], Kb + (2 * j + 1) * 1152 + 64);
            #pragma unroll
            for (int ks = 0; ks < 4; ks++) {
                mma_h(s0, qa[ks], kb0[2 * ks], kb0[2 * ks + 1]);
                mma_h(s1, qa[ks], kb1[2 * ks], kb1[2 * ks + 1]);
            }
            pa[j][0] = hex2(s0[0]);
            pa[j][1] = hex2(s0[1]);
            pa[j][2] = hex2(s1[0]);
            pa[j][3] = hex2(s1[1]);
        }
        {
            __half2 a0 = __hadd2(__hadd2(uh2(pa[0][0]), uh2(pa[0][2])),
                                 __hadd2(uh2(pa[1][0]), uh2(pa[1][2])));
            __half2 a1 = __hadd2(__hadd2(uh2(pa[2][0]), uh2(pa[2][2])),
                                 __hadd2(uh2(pa[3][0]), uh2(pa[3][2])));
            float2 f0 = __half22float2(__hadd2(a0, a1));
            den0 += f0.x + f0.y;
            __half2 b0h = __hadd2(__hadd2(uh2(pa[0][1]), uh2(pa[0][3])),
                                  __hadd2(uh2(pa[1][1]), uh2(pa[1][3])));
            __half2 b1h = __hadd2(__hadd2(uh2(pa[2][1]), uh2(pa[2][3])),
                                  __hadd2(uh2(pa[3][1]), uh2(pa[3][3])));
            float2 f1 = __half22float2(__hadd2(b0h, b1h));
            den1 += f1.x + f1.y;
        }
        #pragma unroll
        for (int dt = 0; dt < 8; dt++) {
            unsigned vb[8];
            ldsm4(vb[0], vb[1], vb[2], vb[3], Vb + dt * 1152);
            ldsm4(vb[4], vb[5], vb[6], vb[7], Vb + dt * 1152 + 64);
            #pragma unroll
            for (int j = 0; j < 4; j++)
                mma_h(oacc[dt], pa[j], vb[2 * j], vb[2 * j + 1]);
        }
    }

    den0 += __shfl_xor_sync(0xffffffffu, den0, 1);
    den0 += __shfl_xor_sync(0xffffffffu, den0, 2);
    den1 += __shfl_xor_sync(0xffffffffu, den1, 1);
    den1 += __shfl_xor_sync(0xffffffffu, den1, 2);
    float i0 = 1.f / den0, i1 = 1.f / den1;

    unsigned af[4][4];
    #pragma unroll
    for (int ks = 0; ks < 4; ks++) {
        af[ks][0] = oacc[2 * ks][0];
        af[ks][1] = oacc[2 * ks][1];
        af[ks][2] = oacc[2 * ks + 1][0];
        af[ks][3] = oacc[2 * ks + 1][1];
    }
    uint32_t Wb = smem_u32(&Wt[0][0]) + lmoff;
    int r0 = qbase + warp * 16 + grp, r1 = r0 + 8;
    float* Yb = g_Y + (size_t)b * 64 * NTOK;
    #pragma unroll
    for (int j = 0; j < 8; j++) {
        unsigned wb[8];
        ldsm4(wb[0], wb[1], wb[2], wb[3], Wb + j * 1152);
        ldsm4(wb[4], wb[5], wb[6], wb[7], Wb + j * 1152 + 64);
        float acc[4] = {0.f, 0.f, 0.f, 0.f};
        #pragma unroll
        for (int ks = 0; ks < 4; ks++)
            mma_hf32(acc, af[ks], wb[2 * ks], wb[2 * ks + 1]);
        int oo = 8 * j + 2 * tig;
        float bz0 = bsm[oo], bz1 = bsm[oo + 1];
        Yb[(size_t)oo * NTOK + r0]       = acc[0] * i0 + bz0;
        Yb[(size_t)(oo + 1) * NTOK + r0] = acc[1] * i0 + bz1;
        Yb[(size_t)oo * NTOK + r1]       = acc[2] * i1 + bz0;
        Yb[(size_t)(oo + 1) * NTOK + r1] = acc[3] * i1 + bz1;
    }
}

// ---------------------------------------------------------------------------
// Stage 3: bilinear 2x (align_corners=False) + LeakyReLU + residual.
// ---------------------------------------------------------------------------
__global__ __launch_bounds__(512) void final_kernel(
    const float* __restrict__ rgb, float* __restrict__ out) {
    int c = blockIdx.x, b = blockIdx.y;
    __shared__ float Ys[64][65];
    int tid = threadIdx.x;

    const float* Yb = g_Y + ((size_t)b * 64 + c) * NTOK;
    for (int i = tid; i < 4096; i += 512) Ys[i >> 6][i & 63] = Yb[i];
    __syncthreads();

    const float* Rb = rgb + ((size_t)b * 64 + c) * 16384;
    float* Ob = out + ((size_t)b * 64 + c) * 16384;

    #pragma unroll
    for (int rep = 0; rep < 8; rep++) {
        int cell = tid + rep * 512;
        int h = cell >> 6, w = cell & 63;
        int hm = max(h - 1, 0), hp = min(h + 1, 63);
        int wm = max(w - 1, 0), wp = min(w + 1, 63);
        float a0 = Ys[hm][wm], a1 = Ys[hm][w], a2 = Ys[hm][wp];
        float b0 = Ys[h][wm],  b1 = Ys[h][w],  b2 = Ys[h][wp];
        float c0 = Ys[hp][wm], c1 = Ys[hp][w], c2 = Ys[hp][wp];
        float u0 = 0.25f * a0 + 0.75f * b0;
        float u1 = 0.25f * a1 + 0.75f * b1;
        float u2 = 0.25f * a2 + 0.75f * b2;
        float d0 = 0.75f * b0 + 0.25f * c0;
        float d1 = 0.75f * b1 + 0.25f * c1;
        float d2 = 0.75f * b2 + 0.25f * c2;
        float o00 = 0.25f * u0 + 0.75f * u1, o01 = 0.75f * u1 + 0.25f * u2;
        float o10 = 0.25f * d0 + 0.75f * d1, o11 = 0.75f * d1 + 0.25f * d2;
        o00 = (o00 >= 0.f) ? o00 : 0.2f * o00;
        o01 = (o01 >= 0.f) ? o01 : 0.2f * o01;
        o10 = (o10 >= 0.f) ? o10 : 0.2f * o10;
        o11 = (o11 >= 0.f) ? o11 : 0.2f * o11;
        float2 r0 = *(const float2*)(Rb + (2 * h) * 128 + 2 * w);
        float2 r1 = *(const float2*)(Rb + (2 * h + 1) * 128 + 2 * w);
        *(float2*)(Ob + (2 * h) * 128 + 2 * w) = make_float2(r0.x + o00, r0.y + o01);
        *(float2*)(Ob + (2 * h + 1) * 128 + 2 * w) = make_float2(r1.x + o10, r1.y + o11);
    }
}

// ---------------------------------------------------------------------------
extern "C" void kernel_launch(void* const* d_in, const int* in_sizes, int n_in,
                              void* d_out, int out_size) {
    const float* rgb   = (const float*)d_in[0];
    const float* freq  = (const float*)d_in[1];
    const float* w_q   = (const float*)d_in[2];
    const float* b_q   = (const float*)d_in[3];
    const float* w_k   = (const float*)d_in[4];
    const float* b_k   = (const float*)d_in[5];
    const float* w_v   = (const float*)d_in[6];
    const float* b_v   = (const float*)d_in[7];
    const float* w_o   = (const float*)d_in[8];
    const float* b_o   = (const float*)d_in[9];
    const float* gamma = (const float*)d_in[10];
    const float* beta  = (const float*)d_in[11];
    const float* mean  = (const float*)d_in[12];
    const float* var   = (const float*)d_in[13];
    float* out = (float*)d_out;

    static bool attr_set = false;
    if (!attr_set) {
        cudaFuncSetAttribute(qkv_kernel,
                             cudaFuncAttributeMaxDynamicSharedMemorySize,
                             QKV_SMEM);
        attr_set = true;
    }

    qkv_kernel<<<dim3(32, 8), 128, QKV_SMEM>>>(rgb, freq, w_q, b_q, w_k, b_k,
                                               w_v, b_v);
    attn_kernel<<<dim3(32, 8), 256>>>(w_o, b_o, gamma, beta, mean, var);
    final_kernel<<<dim3(64, 8), 512>>>(rgb, out);
}